// round 9
// baseline (speedup 1.0000x reference)
#include <cuda_runtime.h>
#include <math.h>

#define TPB 512

// Prologue-computed operands (k-major [k][out])
__device__ float g_P[128*128];   // (Wq^T Wk)/sqrt(d)
__device__ float g_G[128*128];   // Wv^T Theta^T
__device__ float g_U[128*64];    // [k][j]: j<32 -> (W1q@Wq)[j,k], j>=32 -> (W1k@Wk)[j-32,k]

typedef unsigned long long u64;

__device__ __forceinline__ float4 ld4(const float* p){ return *reinterpret_cast<const float4*>(p); }
__device__ __forceinline__ void st4(float* p, float4 v){ *reinterpret_cast<float4*>(p)=v; }
__device__ __forceinline__ u64 ldu(const float* p){ return *reinterpret_cast<const u64*>(p); }
__device__ __forceinline__ void stu(float* p, u64 v){ *reinterpret_cast<u64*>(p)=v; }
__device__ __forceinline__ ulonglong2 ldp2(const float* p){ return *reinterpret_cast<const ulonglong2*>(p); }
__device__ __forceinline__ u64 pk2(float x, float y){ u64 r; asm("mov.b64 %0,{%1,%2};":"=l"(r):"f"(x),"f"(y)); return r; }
__device__ __forceinline__ float2 upk2(u64 v){ float2 f; asm("mov.b64 {%0,%1},%2;":"=f"(f.x),"=f"(f.y):"l"(v)); return f; }
__device__ __forceinline__ u64 fma2(u64 a,u64 b,u64 c){ u64 d; asm("fma.rn.f32x2 %0,%1,%2,%3;":"=l"(d):"l"(a),"l"(b),"l"(c)); return d; }
__device__ __forceinline__ u64 add2(u64 a,u64 b){ u64 d; asm("add.rn.f32x2 %0,%1,%2;":"=l"(d):"l"(a),"l"(b)); return d; }
__device__ __forceinline__ void cpa16(float* dst, const float* src){
    unsigned sa = (unsigned)__cvta_generic_to_shared(dst);
    asm volatile("cp.async.cg.shared.global [%0], [%1], 16;" :: "r"(sa), "l"(src));
}

// ---------------- fast prep (unchanged, measured ~3us) ----------------
__global__ void prep_kernel(const float* __restrict__ Wq, const float* __restrict__ Wk,
                            const float* __restrict__ Wv, const float* __restrict__ Th,
                            const float* __restrict__ W1)
{
    const int bx = blockIdx.x, tid = threadIdx.x;
    if (bx < 128) {
        const int d = bx, k = tid;
        float accP = 0.f, accG = 0.f;
#pragma unroll 8
        for (int i = 0; i < 128; i++) {
            accP = fmaf(Wq[i*128 + k], Wk[i*128 + d], accP);
            accG = fmaf(Wv[i*128 + k], Th[d*128 + i], accG);
        }
        g_P[k*128 + d] = accP * 0.08838834764831845f;
        g_G[k*128 + d] = accG;
    } else {
        const int j = bx - 128, k = tid;
        const float* w1row = (j < 32) ? (W1 + j*260) : (W1 + (j-32)*260 + 128);
        const float* wc    = (j < 32) ? Wq : Wk;
        float acc = 0.f;
#pragma unroll 8
        for (int d = 0; d < 128; d++) acc = fmaf(w1row[d], wc[d*128 + k], acc);
        g_U[k*64 + j] = acc;
    }
}

// -------- shared memory layout (float offsets) -- identical to round 8 --------
#define OZ    0         // Z [32][132] = 4224
#define OC    4224      // C1 -> AZ -> y [32][128] = 4096
#define OST   8320      // staging 2grp x 2buf x [16][64] | ZT [128][33] | HQ[32][36]@+0, HKT[32][33]@+1152
#define OSB   12544     // b1@0, W2@32, mask@64, consts@96, W1e@128
#define OW    12800     // LOG [32][36] = 1152
#define SMEMF 13952     // 55808 bytes -> 3 CTAs/SM (reg-limited), 48 warps/SM

// dst[32x128] = sIn[32x128] @ gW[128][128] (+resid). 512 threads: 2 col-groups x 8 warps,
// each thread 4 rows x 2 cols. cp.async double-buffered [16][64] tiles per group.
__device__ __forceinline__ void gemm_big(const float* __restrict__ sIn, int inStride,
                                         const float* __restrict__ gW,
                                         float* sStage, float* dst,
                                         const float* resid, int residStride, int tid)
{
    const int warp = tid >> 5, lane = tid & 31;
    const int grp = warp >> 3, wg = warp & 7;
    const int r0 = wg * 4;
    const int colbase = grp * 64;
    const int cb = colbase + lane * 2;
    const int gtid = tid & 255;
    const int barid = grp + 1;
    float* sW = sStage + grp * 2048;          // 2 bufs x 1024
    const int l0 = gtid * 4;                  // one float4 per thread per tile
    const int kr0 = l0 >> 6, c0s = l0 & 63;

    u64 acc[4];
#pragma unroll
    for (int i = 0; i < 4; i++) acc[i] = 0ull;

    cpa16(sW + l0, gW + kr0*128 + colbase + c0s);
    asm volatile("cp.async.commit_group;" ::: "memory");

    for (int kt = 0; kt < 8; kt++) {
        const int buf = kt & 1;
        if (kt < 7) {
            const int kb = (kt + 1) * 16;
            cpa16(sW + (buf ^ 1)*1024 + l0, gW + (kb + kr0)*128 + colbase + c0s);
            asm volatile("cp.async.commit_group;" ::: "memory");
            asm volatile("cp.async.wait_group 1;" ::: "memory");
        } else {
            asm volatile("cp.async.wait_group 0;" ::: "memory");
        }
        asm volatile("bar.sync %0, 256;" :: "r"(barid) : "memory");
        const float* w  = sW + buf * 1024;
        const float* zc = sIn + kt * 16;
#pragma unroll
        for (int kk = 0; kk < 16; kk += 4) {
            float4 z[4];
#pragma unroll
            for (int i = 0; i < 4; i++) z[i] = ld4(zc + (r0 + i)*inStride + kk);
#pragma unroll
            for (int u = 0; u < 4; u++) {
                u64 wv = ldu(w + (kk+u)*64 + lane*2);
#pragma unroll
                for (int i = 0; i < 4; i++) {
                    float a = (u==0) ? z[i].x : (u==1) ? z[i].y : (u==2) ? z[i].z : z[i].w;
                    acc[i] = fma2(pk2(a, a), wv, acc[i]);
                }
            }
        }
        asm volatile("bar.sync %0, 256;" :: "r"(barid) : "memory");
    }
    __syncthreads();
#pragma unroll
    for (int i = 0; i < 4; i++) {
        u64 o = acc[i];
        if (resid) o = add2(o, ldu(resid + (r0+i)*residStride + cb));
        stu(dst + (r0+i)*128 + cb, o);
    }
}

__global__ __launch_bounds__(TPB, 3)
void fused_gnn_kernel(const float* __restrict__ x, const float* __restrict__ edge,
                      const float* __restrict__ Aprior, const unsigned char* __restrict__ pmask,
                      const float* __restrict__ Wfuse, const float* __restrict__ W1,
                      const float* __restrict__ b1g, const float* __restrict__ W2g,
                      const float* __restrict__ b2g, const float* __restrict__ gammag,
                      const float* __restrict__ betag, const float* __restrict__ physw,
                      const float* __restrict__ priorw, float* __restrict__ out)
{
    extern __shared__ float sm[];
    const int tid = threadIdx.x;
    const int bt = blockIdx.x;
    const int b = bt >> 6, t = bt & 63;
    const int warp = tid >> 5, lane = tid & 31;

    // ---------------- Phase 0: stage Z (stride 132) + small tensors ----------------
#pragma unroll
    for (int it = 0; it < 2; it++) {
        int idx = tid + it * TPB;              // idx = n*32 + dgroup
        int n = idx >> 5, dg = idx & 31;
        st4(sm + OZ + n*132 + dg*4, ld4(x + ((((size_t)b*32 + n)*64 + t)*128) + dg*4));
    }
    if (tid < 32) {
        sm[OSB + tid]      = b1g[tid];
        sm[OSB + 32 + tid] = W2g[tid];
        sm[OSB + 64 + tid] = pmask[b*32 + tid] ? 1.f : 0.f;
        if (tid == 0) { sm[OSB+96] = physw[0]; sm[OSB+97] = priorw[0]; sm[OSB+98] = b2g[0]; }
    }
    if (tid >= 64 && tid < 192) {              // W1e [j][e]
        int i = tid - 64;
        sm[OSB + 128 + i] = W1[(i>>2)*260 + 256 + (i&3)];
    }
    __syncthreads();

    // ---------------- Phase 1: C1 = Z @ P -> OC ----------------
    gemm_big(sm + OZ, 132, g_P, sm + OST, sm + OC, nullptr, 0, tid);

    // ---------------- Phase 2a: build Z^T in OST (staging now free) ----------------
#pragma unroll
    for (int it = 0; it < 2; it++) {
        int idx = tid + it * TPB;
        int n = idx >> 5, dg = idx & 31;
        float4 v = ld4(sm + OZ + n*132 + dg*4);
        sm[OST + (dg*4+0)*33 + n] = v.x;
        sm[OST + (dg*4+1)*33 + n] = v.y;
        sm[OST + (dg*4+2)*33 + n] = v.z;
        sm[OST + (dg*4+3)*33 + n] = v.w;
    }
    __syncthreads();

    // ---------------- Phase 2b: content = C1 @ Z^T -> LOG (warp owns 2 rows) ----------------
    {
        u64 acc2[2] = {0ull, 0ull};
        for (int k = 0; k < 128; k += 4) {
            u64 zt01 = pk2(sm[OST + (k+0)*33 + lane], sm[OST + (k+1)*33 + lane]);
            u64 zt23 = pk2(sm[OST + (k+2)*33 + lane], sm[OST + (k+3)*33 + lane]);
#pragma unroll
            for (int i = 0; i < 2; i++) {
                ulonglong2 c2 = ldp2(sm + OC + (warp*2+i)*128 + k);
                acc2[i] = fma2(c2.x, zt01, acc2[i]);
                acc2[i] = fma2(c2.y, zt23, acc2[i]);
            }
        }
#pragma unroll
        for (int i = 0; i < 2; i++) {
            float2 f = upk2(acc2[i]);
            sm[OW + (warp*2+i)*36 + lane] = f.x + f.y;
        }
    }
    __syncthreads();   // ZT reads done -> OST reusable for HQ/HKT

    // ---------------- Phase 4: H = Z @ gU (hq | hk), gU streamed from L2 ----------------
    {
        const int grp = warp >> 3, wg = warp & 7;
        const int r0 = wg * 4;
        const int j0g = grp * 32 + lane;
        u64 acc4[2] = {0ull, 0ull};
#pragma unroll 4
        for (int k = 0; k < 128; k += 4) {
            float wr[4];
#pragma unroll
            for (int u = 0; u < 4; u++) wr[u] = __ldg(&g_U[(k+u)*64 + j0g]);
            float4 z[4];
#pragma unroll
            for (int i = 0; i < 4; i++) z[i] = ld4(sm + OZ + (r0 + i)*132 + k);
#pragma unroll
            for (int u = 0; u < 4; u++) {
                u64 w2 = pk2(wr[u], wr[u]);
#pragma unroll
                for (int p = 0; p < 2; p++) {
                    float a0 = (u==0)?z[2*p].x:(u==1)?z[2*p].y:(u==2)?z[2*p].z:z[2*p].w;
                    float a1 = (u==0)?z[2*p+1].x:(u==1)?z[2*p+1].y:(u==2)?z[2*p+1].z:z[2*p+1].w;
                    acc4[p] = fma2(pk2(a0, a1), w2, acc4[p]);
                }
            }
        }
        if (grp == 0) {          // hq -> HQ[32][36] @ OST
#pragma unroll
            for (int p = 0; p < 2; p++) {
                float2 f = upk2(acc4[p]);
                sm[OST + (r0 + 2*p + 0)*36 + j0g] = f.x;
                sm[OST + (r0 + 2*p + 1)*36 + j0g] = f.y;
            }
        } else {                 // hk -> HKT[j][n] [32][33] @ OST+1152
            int j = j0g - 32;
#pragma unroll
            for (int p = 0; p < 2; p++) {
                float2 f = upk2(acc4[p]);
                sm[OST + 1152 + j*33 + (r0 + 2*p + 0)] = f.x;
                sm[OST + 1152 + j*33 + (r0 + 2*p + 1)] = f.y;
            }
        }
    }

    // ---------------- Prefetch edge / prior (2 pairs per thread) ----------------
    const int pn = tid >> 4, pm0 = (tid & 15) << 1;
    float4 e4[2]; float lpr[2];
    {
        const float wf0 = __ldg(Wfuse+0), wf1 = __ldg(Wfuse+1), wf2 = __ldg(Wfuse+2),
                    wf3 = __ldg(Wfuse+3), wf4 = __ldg(Wfuse+4);
#pragma unroll
        for (int mm = 0; mm < 2; mm++) {
            size_t pair = (size_t)bt*1024 + pn*32 + pm0 + mm;
            e4[mm] = ld4(edge + pair*4);
            const float* ap = Aprior + pair*5;
            float p = ap[0]*wf0 + ap[1]*wf1 + ap[2]*wf2 + ap[3]*wf3 + ap[4]*wf4;
            if (!isfinite(p)) p = 0.f;
            p = fmaxf(p, 0.f);
            lpr[mm] = logf(p + 1e-6f);
        }
    }
    __syncthreads();

    // ---------------- Phase 5: phys MLP + prior + logits ----------------
    {
        float ph[2] = {0.f, 0.f};
#pragma unroll
        for (int j = 0; j < 32; j += 4) {
            float4 hqv = ld4(sm + OST + pn*36 + j);
            float4 b1v = ld4(sm + OSB + j);
            float4 w2v = ld4(sm + OSB + 32 + j);
            float hq4[4] = {hqv.x, hqv.y, hqv.z, hqv.w};
            float b14[4] = {b1v.x, b1v.y, b1v.z, b1v.w};
            float w24[4] = {w2v.x, w2v.y, w2v.z, w2v.w};
#pragma unroll
            for (int jj = 0; jj < 4; jj++) {
                int jc = j + jj;
                float hqb = hq4[jj] + b14[jj];
                float w2s = w24[jj];
                float4 we = ld4(sm + OSB + 128 + jc*4);
#pragma unroll
                for (int mm = 0; mm < 2; mm++) {
                    float h = hqb + sm[OST + 1152 + jc*33 + pm0 + mm]
                            + e4[mm].x*we.x + e4[mm].y*we.y
                            + e4[mm].z*we.z + e4[mm].w*we.w;
                    h = fmaxf(h, 0.f);
                    ph[mm] = fmaf(h, w2s, ph[mm]);
                }
            }
        }
        float pw = sm[OSB+96], prw = sm[OSB+97], b2v = sm[OSB+98];
        float mn = sm[OSB + 64 + pn];
#pragma unroll
        for (int mm = 0; mm < 2; mm++) {
            float lg = sm[OW + pn*36 + pm0 + mm]
                     + pw * (ph[mm] + b2v)
                     + prw * lpr[mm];
            if (mn != 0.f || sm[OSB + 64 + pm0 + mm] != 0.f) lg = -1e9f;
            sm[OW + pn*36 + pm0 + mm] = lg;
        }
    }
    __syncthreads();

    // ---------------- Phase 6: softmax (warp per 2 rows) ----------------
#pragma unroll
    for (int q = 0; q < 2; q++) {
        int n = warp*2 + q;
        float v = sm[OW + n*36 + lane];
        float mx = v;
#pragma unroll
        for (int off = 16; off > 0; off >>= 1)
            mx = fmaxf(mx, __shfl_xor_sync(0xffffffffu, mx, off));
        float e = expf(v - mx);
        float s = e;
#pragma unroll
        for (int off = 16; off > 0; off >>= 1)
            s += __shfl_xor_sync(0xffffffffu, s, off);
        sm[OW + n*36 + lane] = e / s;
    }
    __syncthreads();

    // ---------------- Phase 7: AZ = alpha @ Z -> OC ----------------
    {
        const int grp = warp >> 3, wg = warp & 7;
        const int r0 = wg * 4;
        const int cb = grp * 64 + lane * 2;
        u64 acc[4];
#pragma unroll
        for (int i = 0; i < 4; i++) acc[i] = 0ull;
#pragma unroll 2
        for (int k = 0; k < 32; k += 4) {
            float4 a[4];
#pragma unroll
            for (int i = 0; i < 4; i++) a[i] = ld4(sm + OW + (r0 + i)*36 + k);
#pragma unroll
            for (int u = 0; u < 4; u++) {
                u64 zw = ldu(sm + OZ + (k+u)*132 + cb);
#pragma unroll
                for (int i = 0; i < 4; i++) {
                    float av = (u==0) ? a[i].x : (u==1) ? a[i].y : (u==2) ? a[i].z : a[i].w;
                    acc[i] = fma2(pk2(av, av), zw, acc[i]);
                }
            }
        }
        __syncthreads();   // C1 in OC fully consumed (phase 2)
#pragma unroll
        for (int i = 0; i < 4; i++)
            stu(sm + OC + (r0+i)*128 + cb, acc[i]);
    }
    __syncthreads();

    // ---------------- Phase 8: y = Z + AZ @ G -> OC (in-place) ----------------
    gemm_big(sm + OC, 128, g_G, sm + OST, sm + OC, sm + OZ, 132, tid);
    __syncthreads();

    // ---------------- Phase 9: LayerNorm + masked store (warp per 2 rows) ----------------
    {
        float4 gv = __ldg(reinterpret_cast<const float4*>(gammag + lane*4));
        float4 bv = __ldg(reinterpret_cast<const float4*>(betag + lane*4));
#pragma unroll
        for (int q = 0; q < 2; q++) {
            int n = warp*2 + q;
            float4 y = ld4(sm + OC + n*128 + lane*4);
            float s  = y.x + y.y + y.z + y.w;
            float s2 = y.x*y.x + y.y*y.y + y.z*y.z + y.w*y.w;
#pragma unroll
            for (int off = 16; off > 0; off >>= 1) {
                s  += __shfl_xor_sync(0xffffffffu, s, off);
                s2 += __shfl_xor_sync(0xffffffffu, s2, off);
            }
            float mu   = s * (1.f/128.f);
            float var  = s2 * (1.f/128.f) - mu*mu;
            float rstd = rsqrtf(var + 1e-5f);
            float4 o;
            o.x = (y.x - mu)*rstd*gv.x + bv.x;
            o.y = (y.y - mu)*rstd*gv.y + bv.y;
            o.z = (y.z - mu)*rstd*gv.z + bv.z;
            o.w = (y.w - mu)*rstd*gv.w + bv.w;
            if (sm[OSB + 64 + n] != 0.f) o = make_float4(0.f, 0.f, 0.f, 0.f);
            reinterpret_cast<float4*>(out)[(((size_t)b*32 + n)*64 + t)*32 + lane] = o;
        }
    }
}

extern "C" void kernel_launch(void* const* d_in, const int* in_sizes, int n_in,
                              void* d_out, int out_size) {
    (void)in_sizes; (void)n_in; (void)out_size;
    const float* x      = (const float*)d_in[0];
    const float* edge   = (const float*)d_in[1];
    const float* Aprior = (const float*)d_in[2];
    const unsigned char* pmask = (const unsigned char*)d_in[3];
    const float* Wq     = (const float*)d_in[4];
    const float* Wk     = (const float*)d_in[5];
    const float* Wv     = (const float*)d_in[6];
    const float* Th     = (const float*)d_in[7];
    const float* Wfuse  = (const float*)d_in[8];
    const float* W1     = (const float*)d_in[9];
    const float* b1     = (const float*)d_in[10];
    const float* W2     = (const float*)d_in[11];
    const float* b2     = (const float*)d_in[12];
    const float* gamma  = (const float*)d_in[13];
    const float* beta   = (const float*)d_in[14];
    const float* physw  = (const float*)d_in[15];
    const float* priorw = (const float*)d_in[16];
    float* out = (float*)d_out;

    prep_kernel<<<192, 128>>>(Wq, Wk, Wv, Th, W1);

    cudaFuncSetAttribute(fused_gnn_kernel,
                         cudaFuncAttributeMaxDynamicSharedMemorySize, SMEMF * 4);
    fused_gnn_kernel<<<512, TPB, SMEMF * 4>>>(x, edge, Aprior, pmask, Wfuse, W1, b1, W2, b2,
                                              gamma, beta, physw, priorw, out);
}

// round 10
// speedup vs baseline: 1.2035x; 1.2035x over previous
#include <cuda_runtime.h>
#include <math.h>

#define TPB 256

// Prologue-computed operands (k-major [k][out])
__device__ float g_P[128*128];   // (Wq^T Wk)/sqrt(d)
__device__ float g_G[128*128];   // Wv^T Theta^T
__device__ float g_U[128*64];    // [k][j]: j<32 -> (W1q@Wq)[j,k], j>=32 -> (W1k@Wk)[j-32,k]

typedef unsigned long long u64;

__device__ __forceinline__ float4 ld4(const float* p){ return *reinterpret_cast<const float4*>(p); }
__device__ __forceinline__ void st4(float* p, float4 v){ *reinterpret_cast<float4*>(p)=v; }
__device__ __forceinline__ u64 ldu(const float* p){ return *reinterpret_cast<const u64*>(p); }
__device__ __forceinline__ void stu(float* p, u64 v){ *reinterpret_cast<u64*>(p)=v; }
__device__ __forceinline__ ulonglong2 ldp2(const float* p){ return *reinterpret_cast<const ulonglong2*>(p); }
__device__ __forceinline__ void stp2(float* p, u64 a, u64 b){
    ulonglong2 v; v.x = a; v.y = b;
    *reinterpret_cast<ulonglong2*>(p) = v;
}
__device__ __forceinline__ u64 pk2(float x, float y){ u64 r; asm("mov.b64 %0,{%1,%2};":"=l"(r):"f"(x),"f"(y)); return r; }
__device__ __forceinline__ float2 upk2(u64 v){ float2 f; asm("mov.b64 {%0,%1},%2;":"=f"(f.x),"=f"(f.y):"l"(v)); return f; }
__device__ __forceinline__ u64 fma2(u64 a,u64 b,u64 c){ u64 d; asm("fma.rn.f32x2 %0,%1,%2,%3;":"=l"(d):"l"(a),"l"(b),"l"(c)); return d; }
__device__ __forceinline__ u64 add2(u64 a,u64 b){ u64 d; asm("add.rn.f32x2 %0,%1,%2;":"=l"(d):"l"(a),"l"(b)); return d; }
__device__ __forceinline__ void cpa16(float* dst, const float* src){
    unsigned sa = (unsigned)__cvta_generic_to_shared(dst);
    asm volatile("cp.async.cg.shared.global [%0], [%1], 16;" :: "r"(sa), "l"(src));
}

// ---------------- fast prep (unchanged, measured ~3us) ----------------
__global__ void prep_kernel(const float* __restrict__ Wq, const float* __restrict__ Wk,
                            const float* __restrict__ Wv, const float* __restrict__ Th,
                            const float* __restrict__ W1)
{
    const int bx = blockIdx.x, tid = threadIdx.x;
    if (bx < 128) {
        const int d = bx, k = tid;
        float accP = 0.f, accG = 0.f;
#pragma unroll 8
        for (int i = 0; i < 128; i++) {
            accP = fmaf(Wq[i*128 + k], Wk[i*128 + d], accP);
            accG = fmaf(Wv[i*128 + k], Th[d*128 + i], accG);
        }
        g_P[k*128 + d] = accP * 0.08838834764831845f;
        g_G[k*128 + d] = accG;
    } else {
        const int j = bx - 128, k = tid;
        const float* w1row = (j < 32) ? (W1 + j*260) : (W1 + (j-32)*260 + 128);
        const float* wc    = (j < 32) ? Wq : Wk;
        float acc = 0.f;
#pragma unroll 8
        for (int d = 0; d < 128; d++) acc = fmaf(w1row[d], wc[d*128 + k], acc);
        g_U[k*64 + j] = acc;
    }
}

// -------- shared memory layout (float offsets) -- identical to round 8 --------
#define OZ    0         // Z [32][132] = 4224
#define OC    4224      // C1 -> AZ -> y [32][128] = 4096
#define OST   8320      // staging 2buf x [16][128]=4096 | ZT [128][33] | HQ[32][36]@+0, HKT[32][33]@+1152
#define OSB   12544     // b1@0, W2@32, mask@64, consts@96, W1e@128
#define OW    12800     // LOG [32][36] = 1152
#define SMEMF 13952     // 55808 bytes -> 4 CTAs/SM

// dst[32x128] = sIn[32x128] @ gW[128][128] (+resid). 256 threads: warp = 4 rows,
// lane = 4 cols. cp.async double-buffered [16][128] tiles, whole-CTA syncs.
__device__ __forceinline__ void gemm_big(const float* __restrict__ sIn, int inStride,
                                         const float* __restrict__ gW,
                                         float* sStage, float* dst,
                                         const float* resid, int residStride, int tid)
{
    const int warp = tid >> 5, lane = tid & 31;
    const int r0 = warp * 4;
    const int c0 = lane * 4;
    const int off0 = tid * 4;                 // float4 #tid
    const int off1 = off0 + 1024;             // float4 #(tid+256)
    const int kr0 = off0 >> 7, cc0 = off0 & 127;
    const int kr1 = off1 >> 7, cc1 = off1 & 127;

    u64 acc[8];                               // [row 0..3][colpair 0..1]
#pragma unroll
    for (int i = 0; i < 8; i++) acc[i] = 0ull;

    // prologue: stage tile 0 -> buf 0
    cpa16(sStage + off0, gW + kr0*128 + cc0);
    cpa16(sStage + off1, gW + kr1*128 + cc1);
    asm volatile("cp.async.commit_group;" ::: "memory");

    for (int kt = 0; kt < 8; kt++) {
        const int buf = kt & 1;
        if (kt < 7) {
            const int kb = (kt + 1) * 16;
            float* sd = sStage + (buf ^ 1) * 2048;
            cpa16(sd + off0, gW + (kb + kr0)*128 + cc0);
            cpa16(sd + off1, gW + (kb + kr1)*128 + cc1);
            asm volatile("cp.async.commit_group;" ::: "memory");
            asm volatile("cp.async.wait_group 1;" ::: "memory");
        } else {
            asm volatile("cp.async.wait_group 0;" ::: "memory");
        }
        __syncthreads();
        const float* w  = sStage + buf * 2048;
        const float* zc = sIn + kt * 16;
#pragma unroll
        for (int kk = 0; kk < 16; kk += 4) {
            float4 z[4];
#pragma unroll
            for (int i = 0; i < 4; i++) z[i] = ld4(zc + (r0 + i)*inStride + kk);
#pragma unroll
            for (int u = 0; u < 4; u++) {
                ulonglong2 wv = ldp2(w + (kk+u)*128 + c0);
#pragma unroll
                for (int i = 0; i < 4; i++) {
                    float a = (u==0) ? z[i].x : (u==1) ? z[i].y : (u==2) ? z[i].z : z[i].w;
                    u64 ad = pk2(a, a);
                    acc[i*2]   = fma2(ad, wv.x, acc[i*2]);
                    acc[i*2+1] = fma2(ad, wv.y, acc[i*2+1]);
                }
            }
        }
        __syncthreads();    // buf reuse guard (next iter's cp.async overwrites)
    }
#pragma unroll
    for (int i = 0; i < 4; i++) {
        u64 o0 = acc[i*2], o1 = acc[i*2+1];
        if (resid) {
            ulonglong2 r = ldp2(resid + (r0+i)*residStride + c0);
            o0 = add2(o0, r.x);
            o1 = add2(o1, r.y);
        }
        stp2(dst + (r0+i)*128 + c0, o0, o1);
    }
}

__global__ __launch_bounds__(TPB, 4)
void fused_gnn_kernel(const float* __restrict__ x, const float* __restrict__ edge,
                      const float* __restrict__ Aprior, const unsigned char* __restrict__ pmask,
                      const float* __restrict__ Wfuse, const float* __restrict__ W1,
                      const float* __restrict__ b1g, const float* __restrict__ W2g,
                      const float* __restrict__ b2g, const float* __restrict__ gammag,
                      const float* __restrict__ betag, const float* __restrict__ physw,
                      const float* __restrict__ priorw, float* __restrict__ out)
{
    extern __shared__ float sm[];
    const int tid = threadIdx.x;
    const int bt = blockIdx.x;
    const int b = bt >> 6, t = bt & 63;
    const int warp = tid >> 5, lane = tid & 31;

    // ---------------- Phase 0: stage Z (stride 132) + small tensors ----------------
#pragma unroll
    for (int it = 0; it < 4; it++) {
        int idx = tid + it * TPB;              // idx = n*32 + dgroup
        int n = idx >> 5, dg = idx & 31;
        st4(sm + OZ + n*132 + dg*4, ld4(x + ((((size_t)b*32 + n)*64 + t)*128) + dg*4));
    }
    if (tid < 32) {
        sm[OSB + tid]      = b1g[tid];
        sm[OSB + 32 + tid] = W2g[tid];
        sm[OSB + 64 + tid] = pmask[b*32 + tid] ? 1.f : 0.f;
        if (tid == 0) { sm[OSB+96] = physw[0]; sm[OSB+97] = priorw[0]; sm[OSB+98] = b2g[0]; }
    }
    if (tid >= 64 && tid < 192) {              // W1e [j][e]
        int i = tid - 64;
        sm[OSB + 128 + i] = W1[(i>>2)*260 + 256 + (i&3)];
    }
    __syncthreads();

    // ---------------- Phase 1: C1 = Z @ P -> OC ----------------
    gemm_big(sm + OZ, 132, g_P, sm + OST, sm + OC, nullptr, 0, tid);

    // ---------------- Phase 2a: build Z^T in OST (staging now free) ----------------
#pragma unroll
    for (int it = 0; it < 4; it++) {
        int idx = tid + it * TPB;
        int n = idx >> 5, dg = idx & 31;
        float4 v = ld4(sm + OZ + n*132 + dg*4);
        sm[OST + (dg*4+0)*33 + n] = v.x;
        sm[OST + (dg*4+1)*33 + n] = v.y;
        sm[OST + (dg*4+2)*33 + n] = v.z;
        sm[OST + (dg*4+3)*33 + n] = v.w;
    }
    __syncthreads();

    // ---------------- Phase 2b: content = C1 @ Z^T -> LOG ----------------
    {
        u64 acc2[4] = {0ull, 0ull, 0ull, 0ull};
        for (int k = 0; k < 128; k += 4) {
            u64 zt01 = pk2(sm[OST + (k+0)*33 + lane], sm[OST + (k+1)*33 + lane]);
            u64 zt23 = pk2(sm[OST + (k+2)*33 + lane], sm[OST + (k+3)*33 + lane]);
#pragma unroll
            for (int i = 0; i < 4; i++) {
                ulonglong2 c2 = ldp2(sm + OC + (warp*4+i)*128 + k);
                acc2[i] = fma2(c2.x, zt01, acc2[i]);
                acc2[i] = fma2(c2.y, zt23, acc2[i]);
            }
        }
#pragma unroll
        for (int i = 0; i < 4; i++) {
            float2 f = upk2(acc2[i]);
            sm[OW + (warp*4+i)*36 + lane] = f.x + f.y;
        }
    }
    __syncthreads();   // ZT reads done -> OST reusable for HQ/HKT

    // ---------------- Phase 4: H = Z @ gU (hq | hk), gU streamed from L2 ----------------
    {
        const int grp = warp >> 2, wg = warp & 3;
        const int r0 = wg * 8;
        const int j0g = grp * 32 + lane;
        u64 acc4[4] = {0ull, 0ull, 0ull, 0ull};
#pragma unroll 4
        for (int k = 0; k < 128; k += 4) {
            float wr[4];
#pragma unroll
            for (int u = 0; u < 4; u++) wr[u] = __ldg(&g_U[(k+u)*64 + j0g]);
#pragma unroll
            for (int h = 0; h < 2; h++) {
                float4 z[4];
#pragma unroll
                for (int i = 0; i < 4; i++) z[i] = ld4(sm + OZ + (r0 + h*4 + i)*132 + k);
#pragma unroll
                for (int u = 0; u < 4; u++) {
                    u64 w2 = pk2(wr[u], wr[u]);
#pragma unroll
                    for (int p = 0; p < 2; p++) {
                        float a0 = (u==0)?z[2*p].x:(u==1)?z[2*p].y:(u==2)?z[2*p].z:z[2*p].w;
                        float a1 = (u==0)?z[2*p+1].x:(u==1)?z[2*p+1].y:(u==2)?z[2*p+1].z:z[2*p+1].w;
                        acc4[h*2+p] = fma2(pk2(a0, a1), w2, acc4[h*2+p]);
                    }
                }
            }
        }
        if (grp == 0) {          // hq -> HQ[32][36] @ OST
#pragma unroll
            for (int p = 0; p < 4; p++) {
                float2 f = upk2(acc4[p]);
                sm[OST + (r0 + 2*p + 0)*36 + j0g] = f.x;
                sm[OST + (r0 + 2*p + 1)*36 + j0g] = f.y;
            }
        } else {                 // hk -> HKT[j][n] [32][33] @ OST+1152
            int j = j0g - 32;
#pragma unroll
            for (int p = 0; p < 4; p++) {
                float2 f = upk2(acc4[p]);
                sm[OST + 1152 + j*33 + (r0 + 2*p + 0)] = f.x;
                sm[OST + 1152 + j*33 + (r0 + 2*p + 1)] = f.y;
            }
        }
    }

    // ---------------- Prefetch edge / prior ----------------
    const int pn = tid >> 3, pm0 = (tid & 7) << 2;
    float4 e4[4]; float lpr[4];
    {
        const float wf0 = __ldg(Wfuse+0), wf1 = __ldg(Wfuse+1), wf2 = __ldg(Wfuse+2),
                    wf3 = __ldg(Wfuse+3), wf4 = __ldg(Wfuse+4);
#pragma unroll
        for (int mm = 0; mm < 4; mm++) {
            size_t pair = (size_t)bt*1024 + pn*32 + pm0 + mm;
            e4[mm] = ld4(edge + pair*4);
            const float* ap = Aprior + pair*5;
            float p = ap[0]*wf0 + ap[1]*wf1 + ap[2]*wf2 + ap[3]*wf3 + ap[4]*wf4;
            if (!isfinite(p)) p = 0.f;
            p = fmaxf(p, 0.f);
            lpr[mm] = logf(p + 1e-6f);
        }
    }
    __syncthreads();

    // ---------------- Phase 5: phys MLP + prior + logits ----------------
    {
        float ph[4] = {0.f, 0.f, 0.f, 0.f};
#pragma unroll
        for (int j = 0; j < 32; j += 4) {
            float4 hqv = ld4(sm + OST + pn*36 + j);
            float4 b1v = ld4(sm + OSB + j);
            float4 w2v = ld4(sm + OSB + 32 + j);
            float hq4[4] = {hqv.x, hqv.y, hqv.z, hqv.w};
            float b14[4] = {b1v.x, b1v.y, b1v.z, b1v.w};
            float w24[4] = {w2v.x, w2v.y, w2v.z, w2v.w};
#pragma unroll
            for (int jj = 0; jj < 4; jj++) {
                int jc = j + jj;
                float hqb = hq4[jj] + b14[jj];
                float w2s = w24[jj];
                float4 we = ld4(sm + OSB + 128 + jc*4);
#pragma unroll
                for (int mm = 0; mm < 4; mm++) {
                    float h = hqb + sm[OST + 1152 + jc*33 + pm0 + mm]
                            + e4[mm].x*we.x + e4[mm].y*we.y
                            + e4[mm].z*we.z + e4[mm].w*we.w;
                    h = fmaxf(h, 0.f);
                    ph[mm] = fmaf(h, w2s, ph[mm]);
                }
            }
        }
        float pw = sm[OSB+96], prw = sm[OSB+97], b2v = sm[OSB+98];
        float mn = sm[OSB + 64 + pn];
#pragma unroll
        for (int mm = 0; mm < 4; mm++) {
            float lg = sm[OW + pn*36 + pm0 + mm]
                     + pw * (ph[mm] + b2v)
                     + prw * lpr[mm];
            if (mn != 0.f || sm[OSB + 64 + pm0 + mm] != 0.f) lg = -1e9f;
            sm[OW + pn*36 + pm0 + mm] = lg;
        }
    }
    __syncthreads();

    // ---------------- Phase 6: softmax (warp per 4 rows) ----------------
#pragma unroll
    for (int q = 0; q < 4; q++) {
        int n = warp*4 + q;
        float v = sm[OW + n*36 + lane];
        float mx = v;
#pragma unroll
        for (int off = 16; off > 0; off >>= 1)
            mx = fmaxf(mx, __shfl_xor_sync(0xffffffffu, mx, off));
        float e = expf(v - mx);
        float s = e;
#pragma unroll
        for (int off = 16; off > 0; off >>= 1)
            s += __shfl_xor_sync(0xffffffffu, s, off);
        sm[OW + n*36 + lane] = e / s;
    }
    __syncthreads();

    // ---------------- Phase 7: AZ = alpha @ Z -> OC (4 rows x 4 cols per thread) ----------------
    {
        const int r0 = warp * 4;
        const int c0 = lane * 4;
        u64 acc[8];
#pragma unroll
        for (int i = 0; i < 8; i++) acc[i] = 0ull;
#pragma unroll 2
        for (int k = 0; k < 32; k += 4) {
            float4 a[4];
#pragma unroll
            for (int i = 0; i < 4; i++) a[i] = ld4(sm + OW + (r0 + i)*36 + k);
#pragma unroll
            for (int u = 0; u < 4; u++) {
                ulonglong2 zv = ldp2(sm + OZ + (k+u)*132 + c0);
#pragma unroll
                for (int i = 0; i < 4; i++) {
                    float av = (u==0) ? a[i].x : (u==1) ? a[i].y : (u==2) ? a[i].z : a[i].w;
                    u64 ad = pk2(av, av);
                    acc[i*2]   = fma2(ad, zv.x, acc[i*2]);
                    acc[i*2+1] = fma2(ad, zv.y, acc[i*2+1]);
                }
            }
        }
        __syncthreads();   // C1 in OC fully consumed (phase 2)
#pragma unroll
        for (int i = 0; i < 4; i++)
            stp2(sm + OC + (r0+i)*128 + c0, acc[i*2], acc[i*2+1]);
    }
    __syncthreads();

    // ---------------- Phase 8: y = Z + AZ @ G -> OC (in-place) ----------------
    gemm_big(sm + OC, 128, g_G, sm + OST, sm + OC, sm + OZ, 132, tid);
    __syncthreads();

    // ---------------- Phase 9: LayerNorm + masked store ----------------
    {
        float4 gv = __ldg(reinterpret_cast<const float4*>(gammag + lane*4));
        float4 bv = __ldg(reinterpret_cast<const float4*>(betag + lane*4));
#pragma unroll
        for (int q = 0; q < 4; q++) {
            int n = warp*4 + q;
            float4 y = ld4(sm + OC + n*128 + lane*4);
            float s  = y.x + y.y + y.z + y.w;
            float s2 = y.x*y.x + y.y*y.y + y.z*y.z + y.w*y.w;
#pragma unroll
            for (int off = 16; off > 0; off >>= 1) {
                s  += __shfl_xor_sync(0xffffffffu, s, off);
                s2 += __shfl_xor_sync(0xffffffffu, s2, off);
            }
            float mu   = s * (1.f/128.f);
            float var  = s2 * (1.f/128.f) - mu*mu;
            float rstd = rsqrtf(var + 1e-5f);
            float4 o;
            o.x = (y.x - mu)*rstd*gv.x + bv.x;
            o.y = (y.y - mu)*rstd*gv.y + bv.y;
            o.z = (y.z - mu)*rstd*gv.z + bv.z;
            o.w = (y.w - mu)*rstd*gv.w + bv.w;
            if (sm[OSB + 64 + n] != 0.f) o = make_float4(0.f, 0.f, 0.f, 0.f);
            reinterpret_cast<float4*>(out)[(((size_t)b*32 + n)*64 + t)*32 + lane] = o;
        }
    }
}

extern "C" void kernel_launch(void* const* d_in, const int* in_sizes, int n_in,
                              void* d_out, int out_size) {
    (void)in_sizes; (void)n_in; (void)out_size;
    const float* x      = (const float*)d_in[0];
    const float* edge   = (const float*)d_in[1];
    const float* Aprior = (const float*)d_in[2];
    const unsigned char* pmask = (const unsigned char*)d_in[3];
    const float* Wq     = (const float*)d_in[4];
    const float* Wk     = (const float*)d_in[5];
    const float* Wv     = (const float*)d_in[6];
    const float* Th     = (const float*)d_in[7];
    const float* Wfuse  = (const float*)d_in[8];
    const float* W1     = (const float*)d_in[9];
    const float* b1     = (const float*)d_in[10];
    const float* W2     = (const float*)d_in[11];
    const float* b2     = (const float*)d_in[12];
    const float* gamma  = (const float*)d_in[13];
    const float* beta   = (const float*)d_in[14];
    const float* physw  = (const float*)d_in[15];
    const float* priorw = (const float*)d_in[16];
    float* out = (float*)d_out;

    prep_kernel<<<192, 128>>>(Wq, Wk, Wv, Th, W1);

    cudaFuncSetAttribute(fused_gnn_kernel,
                         cudaFuncAttributeMaxDynamicSharedMemorySize, SMEMF * 4);
    fused_gnn_kernel<<<512, TPB, SMEMF * 4>>>(x, edge, Aprior, pmask, Wfuse, W1, b1, W2, b2,
                                              gamma, beta, physw, priorw, out);
}

// round 11
// speedup vs baseline: 1.2586x; 1.0458x over previous
#include <cuda_runtime.h>
#include <math.h>

#define TPB 256

// Prologue-computed operands (k-major [k][out])
__device__ float g_P[128*128];   // (Wq^T Wk)/sqrt(d)
__device__ float g_G[128*128];   // Wv^T Theta^T
__device__ float g_U[128*64];    // [k][j]: j<32 -> (W1q@Wq)[j,k], j>=32 -> (W1k@Wk)[j-32,k]

typedef unsigned long long u64;

__device__ __forceinline__ float4 ld4(const float* p){ return *reinterpret_cast<const float4*>(p); }
__device__ __forceinline__ void st4(float* p, float4 v){ *reinterpret_cast<float4*>(p)=v; }
__device__ __forceinline__ u64 ldu(const float* p){ return *reinterpret_cast<const u64*>(p); }
__device__ __forceinline__ void stu(float* p, u64 v){ *reinterpret_cast<u64*>(p)=v; }
__device__ __forceinline__ ulonglong2 ldp2(const float* p){ return *reinterpret_cast<const ulonglong2*>(p); }
__device__ __forceinline__ void stp2(float* p, u64 a, u64 b){
    ulonglong2 v; v.x = a; v.y = b;
    *reinterpret_cast<ulonglong2*>(p) = v;
}
__device__ __forceinline__ u64 pk2(float x, float y){ u64 r; asm("mov.b64 %0,{%1,%2};":"=l"(r):"f"(x),"f"(y)); return r; }
__device__ __forceinline__ float2 upk2(u64 v){ float2 f; asm("mov.b64 {%0,%1},%2;":"=f"(f.x),"=f"(f.y):"l"(v)); return f; }
__device__ __forceinline__ u64 fma2(u64 a,u64 b,u64 c){ u64 d; asm("fma.rn.f32x2 %0,%1,%2,%3;":"=l"(d):"l"(a),"l"(b),"l"(c)); return d; }
__device__ __forceinline__ u64 add2(u64 a,u64 b){ u64 d; asm("add.rn.f32x2 %0,%1,%2;":"=l"(d):"l"(a),"l"(b)); return d; }

// ---------------- fast prep (unchanged, measured ~3us) ----------------
__global__ void prep_kernel(const float* __restrict__ Wq, const float* __restrict__ Wk,
                            const float* __restrict__ Wv, const float* __restrict__ Th,
                            const float* __restrict__ W1)
{
    const int bx = blockIdx.x, tid = threadIdx.x;
    if (bx < 128) {
        const int d = bx, k = tid;
        float accP = 0.f, accG = 0.f;
#pragma unroll 8
        for (int i = 0; i < 128; i++) {
            accP = fmaf(Wq[i*128 + k], Wk[i*128 + d], accP);
            accG = fmaf(Wv[i*128 + k], Th[d*128 + i], accG);
        }
        g_P[k*128 + d] = accP * 0.08838834764831845f;
        g_G[k*128 + d] = accG;
    } else {
        const int j = bx - 128, k = tid;
        const float* w1row = (j < 32) ? (W1 + j*260) : (W1 + (j-32)*260 + 128);
        const float* wc    = (j < 32) ? Wq : Wk;
        float acc = 0.f;
#pragma unroll 8
        for (int d = 0; d < 128; d++) acc = fmaf(w1row[d], wc[d*128 + k], acc);
        g_U[k*64 + j] = acc;
    }
}

// -------- shared memory layout (float offsets) -- identical to round 10 --------
#define OZ    0         // Z [32][132] = 4224
#define OC    4224      // C1 -> AZ -> y [32][128] = 4096
#define OST   8320      // staging 2buf x [16][128]=4096 | ZTP u64[64][33]=4224 | HQ[32][36]@+0, HKT[32][33]@+1152
#define OSB   12544     // b1@0, W2@32, mask@64, consts@96, W1e@128
#define OW    12800     // LOG [32][36] = 1152
#define SMEMF 13952     // 55808 bytes -> 4 CTAs/SM

// dst[32x128] = sIn[32x128] @ gW[128][128] (+resid). 256 threads: warp = 4 rows,
// lane = 4 cols. Register-prefetch LDG pipeline, ONE __syncthreads per tile.
__device__ __forceinline__ void gemm_big(const float* __restrict__ sIn, int inStride,
                                         const float* __restrict__ gW,
                                         float* sStage, float* dst,
                                         const float* resid, int residStride, int tid)
{
    const int warp = tid >> 5, lane = tid & 31;
    const int r0 = warp * 4;
    const int c0 = lane * 4;
    const int off0 = tid * 4;                 // float4 #tid in [16][128] tile
    const int off1 = off0 + 1024;             // float4 #(tid+256)
    const int kr0 = off0 >> 7, cc0 = off0 & 127;
    const int kr1 = off1 >> 7, cc1 = off1 & 127;

    u64 acc[8];                               // [row 0..3][colpair 0..1]
#pragma unroll
    for (int i = 0; i < 8; i++) acc[i] = 0ull;

    // prologue: tile 0 -> buf 0 (LDG -> regs -> STS)
    float4 p0 = ld4(gW + kr0*128 + cc0);
    float4 p1 = ld4(gW + kr1*128 + cc1);
    st4(sStage + off0, p0);
    st4(sStage + off1, p1);
    __syncthreads();

    for (int kt = 0; kt < 8; kt++) {
        const int buf = kt & 1;
        if (kt < 7) {           // prefetch next tile into registers (hidden by compute)
            const int kb = (kt + 1) * 16;
            p0 = ld4(gW + (kb + kr0)*128 + cc0);
            p1 = ld4(gW + (kb + kr1)*128 + cc1);
        }
        const float* w  = sStage + buf * 2048;
        const float* zc = sIn + kt * 16;
#pragma unroll
        for (int kk = 0; kk < 16; kk += 4) {
            float4 z[4];
#pragma unroll
            for (int i = 0; i < 4; i++) z[i] = ld4(zc + (r0 + i)*inStride + kk);
#pragma unroll
            for (int u = 0; u < 4; u++) {
                ulonglong2 wv = ldp2(w + (kk+u)*128 + c0);
#pragma unroll
                for (int i = 0; i < 4; i++) {
                    float a = (u==0) ? z[i].x : (u==1) ? z[i].y : (u==2) ? z[i].z : z[i].w;
                    u64 ad = pk2(a, a);
                    acc[i*2]   = fma2(ad, wv.x, acc[i*2]);
                    acc[i*2+1] = fma2(ad, wv.y, acc[i*2+1]);
                }
            }
        }
        if (kt < 7) {           // registers -> other buffer (no read hazard: regs held through compute)
            float* sd = sStage + (buf ^ 1) * 2048;
            st4(sd + off0, p0);
            st4(sd + off1, p1);
            __syncthreads();
        }
    }
    __syncthreads();            // all compute done before caller reuses staging
#pragma unroll
    for (int i = 0; i < 4; i++) {
        u64 o0 = acc[i*2], o1 = acc[i*2+1];
        if (resid) {
            ulonglong2 r = ldp2(resid + (r0+i)*residStride + c0);
            o0 = add2(o0, r.x);
            o1 = add2(o1, r.y);
        }
        stp2(dst + (r0+i)*128 + c0, o0, o1);
    }
}

__global__ __launch_bounds__(TPB, 4)
void fused_gnn_kernel(const float* __restrict__ x, const float* __restrict__ edge,
                      const float* __restrict__ Aprior, const unsigned char* __restrict__ pmask,
                      const float* __restrict__ Wfuse, const float* __restrict__ W1,
                      const float* __restrict__ b1g, const float* __restrict__ W2g,
                      const float* __restrict__ b2g, const float* __restrict__ gammag,
                      const float* __restrict__ betag, const float* __restrict__ physw,
                      const float* __restrict__ priorw, float* __restrict__ out)
{
    extern __shared__ float sm[];
    const int tid = threadIdx.x;
    const int bt = blockIdx.x;
    const int b = bt >> 6, t = bt & 63;
    const int warp = tid >> 5, lane = tid & 31;

    // ---------------- Phase 0: stage Z (stride 132) + small tensors ----------------
#pragma unroll
    for (int it = 0; it < 4; it++) {
        int idx = tid + it * TPB;              // idx = n*32 + dgroup
        int n = idx >> 5, dg = idx & 31;
        st4(sm + OZ + n*132 + dg*4, ld4(x + ((((size_t)b*32 + n)*64 + t)*128) + dg*4));
    }
    if (tid < 32) {
        sm[OSB + tid]      = b1g[tid];
        sm[OSB + 32 + tid] = W2g[tid];
        sm[OSB + 64 + tid] = pmask[b*32 + tid] ? 1.f : 0.f;
        if (tid == 0) { sm[OSB+96] = physw[0]; sm[OSB+97] = priorw[0]; sm[OSB+98] = b2g[0]; }
    }
    if (tid >= 64 && tid < 192) {              // W1e [j][e]
        int i = tid - 64;
        sm[OSB + 128 + i] = W1[(i>>2)*260 + 256 + (i&3)];
    }
    __syncthreads();

    // ---------------- Phase 1: C1 = Z @ P -> OC ----------------
    gemm_big(sm + OZ, 132, g_P, sm + OST, sm + OC, nullptr, 0, tid);

    // ---------------- Phase 2a: build packed Z^T (ZTP u64[64][33]) in OST ----------------
#pragma unroll
    for (int it = 0; it < 4; it++) {
        int idx = tid + it * TPB;
        int n = idx >> 5, dg = idx & 31;
        float4 v = ld4(sm + OZ + n*132 + dg*4);
        stu(sm + OST + (dg*2 + 0)*66 + n*2, pk2(v.x, v.y));
        stu(sm + OST + (dg*2 + 1)*66 + n*2, pk2(v.z, v.w));
    }
    __syncthreads();

    // ---------------- Phase 2b: content = C1 @ Z^T -> LOG ----------------
    {
        u64 acc2[4] = {0ull, 0ull, 0ull, 0ull};
        for (int k = 0; k < 128; k += 4) {
            u64 zt01 = ldu(sm + OST + k*33      + lane*2);   // (k/2)*66 = k*33
            u64 zt23 = ldu(sm + OST + k*33 + 66 + lane*2);
#pragma unroll
            for (int i = 0; i < 4; i++) {
                ulonglong2 c2 = ldp2(sm + OC + (warp*4+i)*128 + k);
                acc2[i] = fma2(c2.x, zt01, acc2[i]);
                acc2[i] = fma2(c2.y, zt23, acc2[i]);
            }
        }
#pragma unroll
        for (int i = 0; i < 4; i++) {
            float2 f = upk2(acc2[i]);
            sm[OW + (warp*4+i)*36 + lane] = f.x + f.y;
        }
    }
    __syncthreads();   // ZTP reads done -> OST reusable for HQ/HKT

    // ---------------- Phase 4: H = Z @ gU (hq | hk) -- warp=4 rows, lane=j-pair ----------------
    {
        const int r0 = warp * 4;
        const int j2 = lane * 2;
        u64 acc4[4] = {0ull, 0ull, 0ull, 0ull};
#pragma unroll 4
        for (int k = 0; k < 128; k += 4) {
            u64 wr[4];
#pragma unroll
            for (int u = 0; u < 4; u++) wr[u] = ldu(&g_U[(k+u)*64 + j2]);
            float4 z[4];
#pragma unroll
            for (int i = 0; i < 4; i++) z[i] = ld4(sm + OZ + (r0 + i)*132 + k);
#pragma unroll
            for (int u = 0; u < 4; u++) {
#pragma unroll
                for (int i = 0; i < 4; i++) {
                    float a = (u==0) ? z[i].x : (u==1) ? z[i].y : (u==2) ? z[i].z : z[i].w;
                    acc4[i] = fma2(pk2(a, a), wr[u], acc4[i]);
                }
            }
        }
#pragma unroll
        for (int i = 0; i < 4; i++) {
            int n = r0 + i;
            if (j2 < 32) {                       // hq -> HQ[32][36] @ OST
                stu(sm + OST + n*36 + j2, acc4[i]);
            } else {                             // hk -> HKT[j][n] [32][33] @ OST+1152
                float2 f = upk2(acc4[i]);
                int j = j2 - 32;
                sm[OST + 1152 + (j+0)*33 + n] = f.x;
                sm[OST + 1152 + (j+1)*33 + n] = f.y;
            }
        }
    }

    // ---------------- Prefetch edge / prior ----------------
    const int pn = tid >> 3, pm0 = (tid & 7) << 2;
    float4 e4[4]; float lpr[4];
    {
        const float wf0 = __ldg(Wfuse+0), wf1 = __ldg(Wfuse+1), wf2 = __ldg(Wfuse+2),
                    wf3 = __ldg(Wfuse+3), wf4 = __ldg(Wfuse+4);
#pragma unroll
        for (int mm = 0; mm < 4; mm++) {
            size_t pair = (size_t)bt*1024 + pn*32 + pm0 + mm;
            e4[mm] = ld4(edge + pair*4);
            const float* ap = Aprior + pair*5;
            float p = ap[0]*wf0 + ap[1]*wf1 + ap[2]*wf2 + ap[3]*wf3 + ap[4]*wf4;
            if (!isfinite(p)) p = 0.f;
            p = fmaxf(p, 0.f);
            lpr[mm] = logf(p + 1e-6f);
        }
    }
    __syncthreads();

    // ---------------- Phase 5: phys MLP + prior + logits ----------------
    {
        float ph[4] = {0.f, 0.f, 0.f, 0.f};
#pragma unroll
        for (int j = 0; j < 32; j += 4) {
            float4 hqv = ld4(sm + OST + pn*36 + j);
            float4 b1v = ld4(sm + OSB + j);
            float4 w2v = ld4(sm + OSB + 32 + j);
            float hq4[4] = {hqv.x, hqv.y, hqv.z, hqv.w};
            float b14[4] = {b1v.x, b1v.y, b1v.z, b1v.w};
            float w24[4] = {w2v.x, w2v.y, w2v.z, w2v.w};
#pragma unroll
            for (int jj = 0; jj < 4; jj++) {
                int jc = j + jj;
                float hqb = hq4[jj] + b14[jj];
                float w2s = w24[jj];
                float4 we = ld4(sm + OSB + 128 + jc*4);
#pragma unroll
                for (int mm = 0; mm < 4; mm++) {
                    float h = hqb + sm[OST + 1152 + jc*33 + pm0 + mm]
                            + e4[mm].x*we.x + e4[mm].y*we.y
                            + e4[mm].z*we.z + e4[mm].w*we.w;
                    h = fmaxf(h, 0.f);
                    ph[mm] = fmaf(h, w2s, ph[mm]);
                }
            }
        }
        float pw = sm[OSB+96], prw = sm[OSB+97], b2v = sm[OSB+98];
        float mn = sm[OSB + 64 + pn];
#pragma unroll
        for (int mm = 0; mm < 4; mm++) {
            float lg = sm[OW + pn*36 + pm0 + mm]
                     + pw * (ph[mm] + b2v)
                     + prw * lpr[mm];
            if (mn != 0.f || sm[OSB + 64 + pm0 + mm] != 0.f) lg = -1e9f;
            sm[OW + pn*36 + pm0 + mm] = lg;
        }
    }
    __syncthreads();

    // ---------------- Phase 6: softmax (warp per 4 rows) ----------------
#pragma unroll
    for (int q = 0; q < 4; q++) {
        int n = warp*4 + q;
        float v = sm[OW + n*36 + lane];
        float mx = v;
#pragma unroll
        for (int off = 16; off > 0; off >>= 1)
            mx = fmaxf(mx, __shfl_xor_sync(0xffffffffu, mx, off));
        float e = expf(v - mx);
        float s = e;
#pragma unroll
        for (int off = 16; off > 0; off >>= 1)
            s += __shfl_xor_sync(0xffffffffu, s, off);
        sm[OW + n*36 + lane] = e / s;
    }
    __syncthreads();

    // ---------------- Phase 7: AZ = alpha @ Z -> OC (4 rows x 4 cols per thread) ----------------
    {
        const int r0 = warp * 4;
        const int c0 = lane * 4;
        u64 acc[8];
#pragma unroll
        for (int i = 0; i < 8; i++) acc[i] = 0ull;
#pragma unroll 2
        for (int k = 0; k < 32; k += 4) {
            float4 a[4];
#pragma unroll
            for (int i = 0; i < 4; i++) a[i] = ld4(sm + OW + (r0 + i)*36 + k);
#pragma unroll
            for (int u = 0; u < 4; u++) {
                ulonglong2 zv = ldp2(sm + OZ + (k+u)*132 + c0);
#pragma unroll
                for (int i = 0; i < 4; i++) {
                    float av = (u==0) ? a[i].x : (u==1) ? a[i].y : (u==2) ? a[i].z : a[i].w;
                    u64 ad = pk2(av, av);
                    acc[i*2]   = fma2(ad, zv.x, acc[i*2]);
                    acc[i*2+1] = fma2(ad, zv.y, acc[i*2+1]);
                }
            }
        }
        __syncthreads();   // C1 in OC fully consumed (phase 2)
#pragma unroll
        for (int i = 0; i < 4; i++)
            stp2(sm + OC + (r0+i)*128 + c0, acc[i*2], acc[i*2+1]);
    }
    __syncthreads();

    // ---------------- Phase 8: y = Z + AZ @ G -> OC (in-place) ----------------
    gemm_big(sm + OC, 128, g_G, sm + OST, sm + OC, sm + OZ, 132, tid);
    __syncthreads();

    // ---------------- Phase 9: LayerNorm + masked store ----------------
    {
        float4 gv = __ldg(reinterpret_cast<const float4*>(gammag + lane*4));
        float4 bv = __ldg(reinterpret_cast<const float4*>(betag + lane*4));
#pragma unroll
        for (int q = 0; q < 4; q++) {
            int n = warp*4 + q;
            float4 y = ld4(sm + OC + n*128 + lane*4);
            float s  = y.x + y.y + y.z + y.w;
            float s2 = y.x*y.x + y.y*y.y + y.z*y.z + y.w*y.w;
#pragma unroll
            for (int off = 16; off > 0; off >>= 1) {
                s  += __shfl_xor_sync(0xffffffffu, s, off);
                s2 += __shfl_xor_sync(0xffffffffu, s2, off);
            }
            float mu   = s * (1.f/128.f);
            float var  = s2 * (1.f/128.f) - mu*mu;
            float rstd = rsqrtf(var + 1e-5f);
            float4 o;
            o.x = (y.x - mu)*rstd*gv.x + bv.x;
            o.y = (y.y - mu)*rstd*gv.y + bv.y;
            o.z = (y.z - mu)*rstd*gv.z + bv.z;
            o.w = (y.w - mu)*rstd*gv.w + bv.w;
            if (sm[OSB + 64 + n] != 0.f) o = make_float4(0.f, 0.f, 0.f, 0.f);
            reinterpret_cast<float4*>(out)[(((size_t)b*32 + n)*64 + t)*32 + lane] = o;
        }
    }
}

extern "C" void kernel_launch(void* const* d_in, const int* in_sizes, int n_in,
                              void* d_out, int out_size) {
    (void)in_sizes; (void)n_in; (void)out_size;
    const float* x      = (const float*)d_in[0];
    const float* edge   = (const float*)d_in[1];
    const float* Aprior = (const float*)d_in[2];
    const unsigned char* pmask = (const unsigned char*)d_in[3];
    const float* Wq     = (const float*)d_in[4];
    const float* Wk     = (const float*)d_in[5];
    const float* Wv     = (const float*)d_in[6];
    const float* Th     = (const float*)d_in[7];
    const float* Wfuse  = (const float*)d_in[8];
    const float* W1     = (const float*)d_in[9];
    const float* b1     = (const float*)d_in[10];
    const float* W2     = (const float*)d_in[11];
    const float* b2     = (const float*)d_in[12];
    const float* gamma  = (const float*)d_in[13];
    const float* beta   = (const float*)d_in[14];
    const float* physw  = (const float*)d_in[15];
    const float* priorw = (const float*)d_in[16];
    float* out = (float*)d_out;

    prep_kernel<<<192, 128>>>(Wq, Wk, Wv, Th, W1);

    cudaFuncSetAttribute(fused_gnn_kernel,
                         cudaFuncAttributeMaxDynamicSharedMemorySize, SMEMF * 4);
    fused_gnn_kernel<<<512, TPB, SMEMF * 4>>>(x, edge, Aprior, pmask, Wfuse, W1, b1, W2, b2,
                                              gamma, beta, physw, priorw, out);
}